// round 16
// baseline (speedup 1.0000x reference)
#include <cuda_runtime.h>
#include <cuda_fp16.h>

#define T_DIM   32
#define N_NODES 10000
#define E_EDGES 160000
#define F_DIM   64
#define TN      (T_DIM * N_NODES)
#define CAP     64                      // max in-degree bucket capacity
#define SROW    72                      // padded smem row (halves)
#define NTILES  2500                    // TN / 128
#define TPB     4                       // tiles per block (gemm)

typedef unsigned long long ull;

// ---- packed f32x2 helpers ----
__device__ __forceinline__ ull pack2(float lo, float hi) {
    ull r; asm("mov.b64 %0, {%1, %2};" : "=l"(r) : "f"(lo), "f"(hi)); return r;
}
__device__ __forceinline__ float2 unpack2(ull v) {
    float2 r; asm("mov.b64 {%0, %1}, %2;" : "=f"(r.x), "=f"(r.y) : "l"(v)); return r;
}
__device__ __forceinline__ ull fma2(ull a, ull b, ull c) {
    ull d; asm("fma.rn.f32x2 %0, %1, %2, %3;" : "=l"(d) : "l"(a), "l"(b), "l"(c)); return d;
}
__device__ __forceinline__ ull add2(ull a, ull b) {
    ull d; asm("add.rn.f32x2 %0, %1, %2;" : "=l"(d) : "l"(a), "l"(b)); return d;
}
__device__ __forceinline__ ull f4_to_h4(float a, float b, float c, float d) {
    __half2 lo = __float22half2_rn(make_float2(a, b));
    __half2 hi = __float22half2_rn(make_float2(c, d));
    ull r;
    asm("mov.b64 %0, {%1, %2};" : "=l"(r)
        : "r"(*(unsigned*)&lo), "r"(*(unsigned*)&hi));
    return r;
}
__device__ __forceinline__ void unpack_u64(ull v, unsigned& lo, unsigned& hi) {
    asm("mov.b64 {%0, %1}, %2;" : "=r"(lo), "=r"(hi) : "l"(v));
}

// ---- tensor-core primitives ----
__device__ __forceinline__ unsigned smem_u32(const void* p) {
    return (unsigned)__cvta_generic_to_shared(p);
}
__device__ __forceinline__ void ldsm_x4_t(unsigned* r, unsigned addr) {
    asm volatile("ldmatrix.sync.aligned.m8n8.x4.trans.shared.b16 {%0,%1,%2,%3}, [%4];"
        : "=r"(r[0]), "=r"(r[1]), "=r"(r[2]), "=r"(r[3]) : "r"(addr));
}
__device__ __forceinline__ void mma_16816(float* c, const unsigned* a,
                                          unsigned b0, unsigned b1) {
    asm volatile("mma.sync.aligned.m16n8k16.row.col.f32.f16.f16.f32 "
        "{%0,%1,%2,%3}, {%4,%5,%6,%7}, {%8,%9}, {%0,%1,%2,%3};"
        : "+f"(c[0]), "+f"(c[1]), "+f"(c[2]), "+f"(c[3])
        : "r"(a[0]), "r"(a[1]), "r"(a[2]), "r"(a[3]), "r"(b0), "r"(b1));
}

// -------- device scratch --------
__device__ int    g_i64flag = 1;   // int64-detect: only ever written to 0
__device__ float  g_deg[N_NODES];
__device__ int    g_count[N_NODES];
__device__ int2   g_csr[N_NODES * CAP];
__device__ __half g_h1[(size_t)TN * F_DIM];           // 40.96 MB
__device__ __half g_h2[(size_t)TN * F_DIM];           // 40.96 MB

__device__ __forceinline__ int edge_src(const void* ei, int e) {
    return g_i64flag ? (int)((const long long*)ei)[e] : ((const int*)ei)[e];
}
__device__ __forceinline__ int edge_dst(const void* ei, int e) {
    return g_i64flag ? (int)((const long long*)ei)[E_EDGES + e]
                     : ((const int*)ei)[E_EDGES + e];
}

// -------- prep --------
__global__ void k_detect_init(const void* __restrict__ ei) {
    int e = blockIdx.x * blockDim.x + threadIdx.x;
    if (e < N_NODES) { g_deg[e] = 0.f; g_count[e] = 0; }
    if (e < E_EDGES) {
        long long v = ((const long long*)ei)[e];   // in-bounds for either dtype
        if (v < 0 || v >= N_NODES) g_i64flag = 0;
    }
}
__global__ void k_hist(const void* __restrict__ ei, const float* __restrict__ ew) {
    int e = blockIdx.x * blockDim.x + threadIdx.x;
    if (e < E_EDGES) atomicAdd(&g_deg[edge_dst(ei, e)], ew[e]);
}
__global__ void k_fill(const void* __restrict__ ei, const float* __restrict__ ew) {
    int e = blockIdx.x * blockDim.x + threadIdx.x;
    if (e < E_EDGES) {
        int src = edge_src(ei, e);
        int dst = edge_dst(ei, e);
        float ds = g_deg[src], dd = g_deg[dst];
        float is = (ds > 0.f) ? rsqrtf(ds) : 0.f;
        float id = (dd > 0.f) ? rsqrtf(dd) : 0.f;
        float nm = is * ew[e] * id;
        int pos = atomicAdd(&g_count[dst], 1);
        if (pos < CAP)
            g_csr[dst * CAP + pos] = make_int2(src, __float_as_int(nm));
    }
}

// ---- W load: 64x64 fp32 -> fp16 padded smem ----
__device__ __forceinline__ void load_w_conv(const float* __restrict__ W,
                                            __half* sW, int tid) {
    int row = tid >> 2, c0 = (tid & 3) * 16;
    const float4* src = (const float4*)(W + row * 64 + c0);
    __half* dst = sW + row * SROW + c0;
    #pragma unroll
    for (int i = 0; i < 2; i++) {
        float4 u = src[2 * i], v = src[2 * i + 1];
        __half2 h0 = __float22half2_rn(make_float2(u.x, u.y));
        __half2 h1 = __float22half2_rn(make_float2(u.z, u.w));
        __half2 h2 = __float22half2_rn(make_float2(v.x, v.y));
        __half2 h3 = __float22half2_rn(make_float2(v.z, v.w));
        uint4 pk = make_uint4(*(unsigned*)&h0, *(unsigned*)&h1,
                              *(unsigned*)&h2, *(unsigned*)&h3);
        *(uint4*)(dst + i * 8) = pk;
    }
}

// ---- MMA + epilogue given 16 A-fragment regs; warp-private staging ----
__device__ __forceinline__ void mma_tile(const unsigned a[4][4], unsigned bBase,
                                         __half* sEw, __half* __restrict__ Out,
                                         size_t rowG, int lane) {
    float c[8][4];
    #pragma unroll
    for (int i = 0; i < 8; i++)
        #pragma unroll
        for (int j = 0; j < 4; j++) c[i][j] = 0.f;

    #pragma unroll
    for (int ks = 0; ks < 4; ks++) {
        #pragma unroll
        for (int ns = 0; ns < 4; ns++) {
            unsigned b[4];
            ldsm_x4_t(b, bBase + (16 * ks * SROW + 16 * ns) * 2);
            mma_16816(c[2 * ns],     a[ks], b[0], b[1]);
            mma_16816(c[2 * ns + 1], a[ks], b[2], b[3]);
        }
    }

    const int g = lane >> 2, t = lane & 3;
    #pragma unroll
    for (int nt = 0; nt < 8; nt++) {
        __half2 lo = __float22half2_rn(make_float2(c[nt][0], c[nt][1]));
        __half2 hi = __float22half2_rn(make_float2(c[nt][2], c[nt][3]));
        *(__half2*)(sEw + g       * SROW + nt * 8 + 2 * t) = lo;
        *(__half2*)(sEw + (8 + g) * SROW + nt * 8 + 2 * t) = hi;
    }
    __syncwarp();
    {
        int r  = lane >> 1;
        int sg = (lane & 1) * 32;
        const uint4* s = (const uint4*)(sEw + r * SROW + sg);
        uint4* d = (uint4*)(Out + (rowG + r) * 64 + sg);
        #pragma unroll
        for (int i = 0; i < 4; i++) d[i] = s[i];
    }
    __syncwarp();
}

// fp32-input GEMM (measured 33.3us): direct-LDG.64 A fragments.
__global__ void __launch_bounds__(256) k_gemm_f32(const float* __restrict__ A,
                                                  const float* __restrict__ W,
                                                  __half* __restrict__ Out) {
    __shared__ __align__(16) __half sW[64 * SROW];          // 9 KB
    __shared__ __align__(16) __half sE[8][16 * SROW];       // 18 KB
    const int tid  = threadIdx.x;
    const int w    = tid >> 5;
    const int lane = tid & 31;
    const int g    = lane >> 2, tg = lane & 3;
    const int grp  = lane >> 3, gr = lane & 7;
    const int tile0 = blockIdx.x * TPB;

    load_w_conv(W, sW, tid);

    const unsigned bBase = smem_u32(sW)
        + ((gr + (grp & 1) * 8) * SROW + (grp >> 1) * 8) * 2;
    __half* sEw = &sE[w][0];
    const int m0 = w * 16;

    float2 raw[16];
    {
        const float* base = A + ((size_t)tile0 * 128 + m0) * 64;
        #pragma unroll
        for (int ks = 0; ks < 4; ks++)
            #pragma unroll
            for (int f = 0; f < 4; f++)
                raw[ks * 4 + f] = __ldg((const float2*)
                    (base + (g + (f & 1) * 8) * 64 + ks * 16 + 2 * tg + (f >> 1) * 8));
    }
    __syncthreads();   // sW ready

    #pragma unroll
    for (int it = 0; it < TPB; it++) {
        unsigned a[4][4];
        #pragma unroll
        for (int ks = 0; ks < 4; ks++)
            #pragma unroll
            for (int f = 0; f < 4; f++) {
                __half2 h = __float22half2_rn(raw[ks * 4 + f]);
                a[ks][f] = *(unsigned*)&h;
            }
        if (it + 1 < TPB) {
            const float* base = A + ((size_t)(tile0 + it + 1) * 128 + m0) * 64;
            #pragma unroll
            for (int ks = 0; ks < 4; ks++)
                #pragma unroll
                for (int f = 0; f < 4; f++)
                    raw[ks * 4 + f] = __ldg((const float2*)
                        (base + (g + (f & 1) * 8) * 64 + ks * 16 + 2 * tg + (f >> 1) * 8));
        }
        mma_tile(a, bBase, sEw, Out, (size_t)(tile0 + it) * 128 + m0, lane);
    }
}

// fp16-input GEMM: A is stored in PERMUTED (fragment-interleaved) layout by
// agg1, so each thread's (a0,a2) / (a1,a3) fragments are one 8B LDG.64.
// Same latency-free structure as k_gemm_f32. Output in TRUE order.
__global__ void __launch_bounds__(256) k_gemm_f16(const __half* __restrict__ A,
                                                  const float* __restrict__ W,
                                                  __half* __restrict__ Out) {
    __shared__ __align__(16) __half sW[64 * SROW];          // 9 KB
    __shared__ __align__(16) __half sE[8][16 * SROW];       // 18 KB
    const int tid  = threadIdx.x;
    const int w    = tid >> 5;
    const int lane = tid & 31;
    const int g    = lane >> 2, tg = lane & 3;
    const int grp  = lane >> 3, gr = lane & 7;
    const int tile0 = blockIdx.x * TPB;

    load_w_conv(W, sW, tid);

    const unsigned bBase = smem_u32(sW)
        + ((gr + (grp & 1) * 8) * SROW + (grp >> 1) * 8) * 2;
    __half* sEw = &sE[w][0];
    const int m0 = w * 16;

    ull raw[8];
    {
        const __half* base = A + ((size_t)tile0 * 128 + m0) * 64;
        #pragma unroll
        for (int ks = 0; ks < 4; ks++)
            #pragma unroll
            for (int r = 0; r < 2; r++)
                raw[ks * 2 + r] = __ldg((const ull*)
                    (base + (g + r * 8) * 64 + ks * 16 + tg * 4));
    }
    __syncthreads();   // sW ready

    #pragma unroll
    for (int it = 0; it < TPB; it++) {
        unsigned a[4][4];
        #pragma unroll
        for (int ks = 0; ks < 4; ks++) {
            unpack_u64(raw[ks * 2 + 0], a[ks][0], a[ks][2]);   // row g:   a0, a2
            unpack_u64(raw[ks * 2 + 1], a[ks][1], a[ks][3]);   // row g+8: a1, a3
        }
        if (it + 1 < TPB) {
            const __half* base = A + ((size_t)(tile0 + it + 1) * 128 + m0) * 64;
            #pragma unroll
            for (int ks = 0; ks < 4; ks++)
                #pragma unroll
                for (int r = 0; r < 2; r++)
                    raw[ks * 2 + r] = __ldg((const ull*)
                        (base + (g + r * 8) * 64 + ks * 16 + tg * 4));
        }
        mma_tile(a, bBase, sEw, Out, (size_t)(tile0 + it) * 128 + m0, lane);
    }
}

// -------- aggregation (R14 config): block = (4 nodes, 8 t-values), tg-major;
// split-lane LDG.64 gathers; fp32 accumulate. Hidden output (out_fp16=1) is
// stored in the PERMUTED fragment layout for k_gemm_f16; final fp32 output
// keeps true order. Column order is irrelevant to the weighted row-sum, so
// permuting only the store is correctness-transparent. --------
__global__ void __launch_bounds__(256) k_agg(const __half* __restrict__ in,
                                             const float* __restrict__ bias,
                                             void* __restrict__ out,
                                             int do_relu, int out_fp16) {
    __shared__ int2 se[4 * CAP];
    __shared__ int  sc[4];
    const int bid  = blockIdx.x;
    const int tg   = bid / (N_NODES / 4);          // 0..3
    const int n0   = (bid - tg * (N_NODES / 4)) * 4;
    const int tid  = threadIdx.x;

    {
        int j = tid >> 6, k = tid & 63;
        int c = g_count[n0 + j];
        if (c > CAP) c = CAP;
        if (k == 0) sc[j] = c;
        if (k < c) se[tid] = g_csr[(n0 + j) * CAP + k];
    }
    __syncthreads();

    const int w    = tid >> 5;
    const int lane = tid & 31;
    const int half = lane >> 4;
    const int hl   = lane & 15;
    const int t    = tg * 8 + w;

    // permuted pair positions for true pairs p0=2*hl, p1=2*hl+1
    // (within k-step: true pair lp -> L pos (lp<4 ? 2*lp : 2*(lp-4)+1))
    const int p0 = 2 * hl,        p1 = 2 * hl + 1;
    const int lp0 = p0 & 7,       lp1 = p1 & 7;
    const int Lp0 = (p0 >> 3) * 8 + ((lp0 < 4) ? 2 * lp0 : 2 * (lp0 - 4) + 1);
    const int Lp1 = (p1 >> 3) * 8 + ((lp1 < 4) ? 2 * lp1 : 2 * (lp1 - 4) + 1);

    const ull* base = (const ull*)(in + (size_t)t * (N_NODES * F_DIM)) + hl;
    const float4 bv = __ldg((const float4*)bias + hl);

    #pragma unroll
    for (int j = 0; j < 4; j++) {
        const int cnt = sc[j];
        const int2* sej = se + j * CAP;

        ull a0 = 0ull, a1 = 0ull, a2 = 0ull, a3 = 0ull;
        int e = 0;
        for (; e + 7 < cnt; e += 8) {
            int2 s0 = sej[e     + half];
            int2 s1 = sej[e + 2 + half];
            int2 s2 = sej[e + 4 + half];
            int2 s3 = sej[e + 6 + half];
            ull v0 = __ldg(base + (unsigned)s0.x * 16u);
            ull v1 = __ldg(base + (unsigned)s1.x * 16u);
            ull v2 = __ldg(base + (unsigned)s2.x * 16u);
            ull v3 = __ldg(base + (unsigned)s3.x * 16u);
            float w0 = __int_as_float(s0.y), w1 = __int_as_float(s1.y);
            float w2 = __int_as_float(s2.y), w3 = __int_as_float(s3.y);
            {   const __half2* h = (const __half2*)&v0;
                float2 f0 = __half22float2(h[0]), f1 = __half22float2(h[1]);
                a0 = fma2(pack2(w0, w0), pack2(f0.x, f0.y), a0);
                a1 = fma2(pack2(w0, w0), pack2(f1.x, f1.y), a1); }
            {   const __half2* h = (const __half2*)&v1;
                float2 f0 = __half22float2(h[0]), f1 = __half22float2(h[1]);
                a2 = fma2(pack2(w1, w1), pack2(f0.x, f0.y), a2);
                a3 = fma2(pack2(w1, w1), pack2(f1.x, f1.y), a3); }
            {   const __half2* h = (const __half2*)&v2;
                float2 f0 = __half22float2(h[0]), f1 = __half22float2(h[1]);
                a0 = fma2(pack2(w2, w2), pack2(f0.x, f0.y), a0);
                a1 = fma2(pack2(w2, w2), pack2(f1.x, f1.y), a1); }
            {   const __half2* h = (const __half2*)&v3;
                float2 f0 = __half22float2(h[0]), f1 = __half22float2(h[1]);
                a2 = fma2(pack2(w3, w3), pack2(f0.x, f0.y), a2);
                a3 = fma2(pack2(w3, w3), pack2(f1.x, f1.y), a3); }
        }
        for (; e < cnt; e += 2) {
            int idx = e + half;
            if (idx < cnt) {
                int2 sn = sej[idx];
                ull v = __ldg(base + (unsigned)sn.x * 16u);
                float ww = __int_as_float(sn.y);
                const __half2* h = (const __half2*)&v;
                float2 f0 = __half22float2(h[0]), f1 = __half22float2(h[1]);
                a0 = fma2(pack2(ww, ww), pack2(f0.x, f0.y), a0);
                a1 = fma2(pack2(ww, ww), pack2(f1.x, f1.y), a1);
            }
        }

        a0 = add2(a0, a2);
        a1 = add2(a1, a3);
        ull b0 = __shfl_down_sync(0xffffffffu, a0, 16);
        ull b1 = __shfl_down_sync(0xffffffffu, a1, 16);
        if (half == 0) {
            a0 = add2(a0, b0);
            a1 = add2(a1, b1);
            float2 p0f = unpack2(a0), p1f = unpack2(a1);
            float4 o = make_float4(p0f.x + bv.x, p0f.y + bv.y,
                                   p1f.x + bv.z, p1f.y + bv.w);
            if (do_relu) {
                o.x = fmaxf(o.x, 0.f); o.y = fmaxf(o.y, 0.f);
                o.z = fmaxf(o.z, 0.f); o.w = fmaxf(o.w, 0.f);
            }
            const size_t rrow = (size_t)t * N_NODES + (n0 + j);
            if (out_fp16) {
                // permuted fragment layout for k_gemm_f16
                __half2* hp = (__half2*)out + rrow * 32;
                hp[Lp0] = __float22half2_rn(make_float2(o.x, o.y));
                hp[Lp1] = __float22half2_rn(make_float2(o.z, o.w));
            } else {
                ((float4*)out)[rrow * 16 + hl] = o;
            }
        }
    }
}

// -------- launch --------
extern "C" void kernel_launch(void* const* d_in, const int* in_sizes, int n_in,
                              void* d_out, int out_size) {
    const float* x   = (const float*)d_in[0];
    const void*  ei  = d_in[1];
    const float* ew  = (const float*)d_in[2];
    const float* W1  = (const float*)d_in[3];
    const float* b1  = (const float*)d_in[4];
    const float* W2  = (const float*)d_in[5];
    const float* b2  = (const float*)d_in[6];
    float*       out = (float*)d_out;

    __half *h1 = nullptr, *h2 = nullptr;
    cudaGetSymbolAddress((void**)&h1, g_h1);
    cudaGetSymbolAddress((void**)&h2, g_h2);

    k_detect_init<<<(E_EDGES + 255) / 256, 256>>>(ei);       // 0
    k_hist       <<<(E_EDGES + 255) / 256, 256>>>(ei, ew);   // 1
    k_fill       <<<(E_EDGES + 255) / 256, 256>>>(ei, ew);   // 2

    // layer 1: h = relu(A (x W1) + b1)   [h stored fp16, PERMUTED layout]
    k_gemm_f32<<<NTILES / TPB, 256>>>(x, W1, h1);            // 3  (ncu target)
    k_agg     <<<(N_NODES / 4) * 4, 256>>>(h1, b1, h2, 1, 1);      // 4
    // layer 2: out = A (h W2) + b2       [final out fp32, true order]
    k_gemm_f16<<<NTILES / TPB, 256>>>(h2, W2, h1);           // 5
    k_agg     <<<(N_NODES / 4) * 4, 256>>>(h1, b2, out, 0, 0);     // 6
}

// round 17
// speedup vs baseline: 1.0679x; 1.0679x over previous
#include <cuda_runtime.h>
#include <cuda_fp16.h>

#define T_DIM   32
#define N_NODES 10000
#define E_EDGES 160000
#define F_DIM   64
#define TN      (T_DIM * N_NODES)
#define CAP     64                      // max in-degree bucket capacity
#define SROW    72                      // padded smem row (halves)
#define NTILES  2500                    // TN / 128
#define TPB     4                       // tiles per block (gemm)

typedef unsigned long long ull;

// ---- packed f32x2 helpers ----
__device__ __forceinline__ ull pack2(float lo, float hi) {
    ull r; asm("mov.b64 %0, {%1, %2};" : "=l"(r) : "f"(lo), "f"(hi)); return r;
}
__device__ __forceinline__ float2 unpack2(ull v) {
    float2 r; asm("mov.b64 {%0, %1}, %2;" : "=f"(r.x), "=f"(r.y) : "l"(v)); return r;
}
__device__ __forceinline__ ull fma2(ull a, ull b, ull c) {
    ull d; asm("fma.rn.f32x2 %0, %1, %2, %3;" : "=l"(d) : "l"(a), "l"(b), "l"(c)); return d;
}
__device__ __forceinline__ ull add2(ull a, ull b) {
    ull d; asm("add.rn.f32x2 %0, %1, %2;" : "=l"(d) : "l"(a), "l"(b)); return d;
}
__device__ __forceinline__ ull f4_to_h4(float a, float b, float c, float d) {
    __half2 lo = __float22half2_rn(make_float2(a, b));
    __half2 hi = __float22half2_rn(make_float2(c, d));
    ull r;
    asm("mov.b64 %0, {%1, %2};" : "=l"(r)
        : "r"(*(unsigned*)&lo), "r"(*(unsigned*)&hi));
    return r;
}
__device__ __forceinline__ void unpack_u64(ull v, unsigned& lo, unsigned& hi) {
    asm("mov.b64 {%0, %1}, %2;" : "=r"(lo), "=r"(hi) : "l"(v));
}

// ---- tensor-core primitives ----
__device__ __forceinline__ unsigned smem_u32(const void* p) {
    return (unsigned)__cvta_generic_to_shared(p);
}
__device__ __forceinline__ void ldsm_x4_t(unsigned* r, unsigned addr) {
    asm volatile("ldmatrix.sync.aligned.m8n8.x4.trans.shared.b16 {%0,%1,%2,%3}, [%4];"
        : "=r"(r[0]), "=r"(r[1]), "=r"(r[2]), "=r"(r[3]) : "r"(addr));
}
__device__ __forceinline__ void mma_16816(float* c, const unsigned* a,
                                          unsigned b0, unsigned b1) {
    asm volatile("mma.sync.aligned.m16n8k16.row.col.f32.f16.f16.f32 "
        "{%0,%1,%2,%3}, {%4,%5,%6,%7}, {%8,%9}, {%0,%1,%2,%3};"
        : "+f"(c[0]), "+f"(c[1]), "+f"(c[2]), "+f"(c[3])
        : "r"(a[0]), "r"(a[1]), "r"(a[2]), "r"(a[3]), "r"(b0), "r"(b1));
}

// -------- device scratch --------
__device__ int    g_i64flag = 1;   // int64-detect: only ever written to 0
__device__ float  g_deg[N_NODES];
__device__ int    g_count[N_NODES];
__device__ int2   g_csr[N_NODES * CAP];
__device__ __half g_h1[(size_t)TN * F_DIM];           // 40.96 MB
__device__ __half g_h2[(size_t)TN * F_DIM];           // 40.96 MB

__device__ __forceinline__ int edge_src(const void* ei, int e) {
    return g_i64flag ? (int)((const long long*)ei)[e] : ((const int*)ei)[e];
}
__device__ __forceinline__ int edge_dst(const void* ei, int e) {
    return g_i64flag ? (int)((const long long*)ei)[E_EDGES + e]
                     : ((const int*)ei)[E_EDGES + e];
}

// -------- prep --------
__global__ void k_detect_init(const void* __restrict__ ei) {
    int e = blockIdx.x * blockDim.x + threadIdx.x;
    if (e < N_NODES) { g_deg[e] = 0.f; g_count[e] = 0; }
    if (e < E_EDGES) {
        long long v = ((const long long*)ei)[e];   // in-bounds for either dtype
        if (v < 0 || v >= N_NODES) g_i64flag = 0;
    }
}
__global__ void k_hist(const void* __restrict__ ei, const float* __restrict__ ew) {
    int e = blockIdx.x * blockDim.x + threadIdx.x;
    if (e < E_EDGES) atomicAdd(&g_deg[edge_dst(ei, e)], ew[e]);
}
__global__ void k_fill(const void* __restrict__ ei, const float* __restrict__ ew) {
    int e = blockIdx.x * blockDim.x + threadIdx.x;
    if (e < E_EDGES) {
        int src = edge_src(ei, e);
        int dst = edge_dst(ei, e);
        float ds = g_deg[src], dd = g_deg[dst];
        float is = (ds > 0.f) ? rsqrtf(ds) : 0.f;
        float id = (dd > 0.f) ? rsqrtf(dd) : 0.f;
        float nm = is * ew[e] * id;
        int pos = atomicAdd(&g_count[dst], 1);
        if (pos < CAP)
            g_csr[dst * CAP + pos] = make_int2(src, __float_as_int(nm));
    }
}

// ---- W load: 64x64 fp32 -> fp16 padded smem ----
__device__ __forceinline__ void load_w_conv(const float* __restrict__ W,
                                            __half* sW, int tid) {
    int row = tid >> 2, c0 = (tid & 3) * 16;
    const float4* src = (const float4*)(W + row * 64 + c0);
    __half* dst = sW + row * SROW + c0;
    #pragma unroll
    for (int i = 0; i < 2; i++) {
        float4 u = src[2 * i], v = src[2 * i + 1];
        __half2 h0 = __float22half2_rn(make_float2(u.x, u.y));
        __half2 h1 = __float22half2_rn(make_float2(u.z, u.w));
        __half2 h2 = __float22half2_rn(make_float2(v.x, v.y));
        __half2 h3 = __float22half2_rn(make_float2(v.z, v.w));
        uint4 pk = make_uint4(*(unsigned*)&h0, *(unsigned*)&h1,
                              *(unsigned*)&h2, *(unsigned*)&h3);
        *(uint4*)(dst + i * 8) = pk;
    }
}

// ---- MMA + epilogue given 16 A-fragment regs; warp-private staging.
// PERM=1: stage output in fragment-interleaved (permuted) column order:
// true pair p = 4*nt + t  ->  half offset (nt>>1)*16 + 4*t + 2*(nt&1).
// PERM=0: true order (half offset nt*8 + 2*t). ----
__device__ __forceinline__ void mma_tile(const unsigned a[4][4], unsigned bBase,
                                         __half* sEw, __half* __restrict__ Out,
                                         size_t rowG, int lane, int PERM) {
    float c[8][4];
    #pragma unroll
    for (int i = 0; i < 8; i++)
        #pragma unroll
        for (int j = 0; j < 4; j++) c[i][j] = 0.f;

    #pragma unroll
    for (int ks = 0; ks < 4; ks++) {
        #pragma unroll
        for (int ns = 0; ns < 4; ns++) {
            unsigned b[4];
            ldsm_x4_t(b, bBase + (16 * ks * SROW + 16 * ns) * 2);
            mma_16816(c[2 * ns],     a[ks], b[0], b[1]);
            mma_16816(c[2 * ns + 1], a[ks], b[2], b[3]);
        }
    }

    const int g = lane >> 2, t = lane & 3;
    #pragma unroll
    for (int nt = 0; nt < 8; nt++) {
        int off = PERM ? ((nt >> 1) * 16 + 4 * t + 2 * (nt & 1))
                       : (nt * 8 + 2 * t);
        __half2 lo = __float22half2_rn(make_float2(c[nt][0], c[nt][1]));
        __half2 hi = __float22half2_rn(make_float2(c[nt][2], c[nt][3]));
        *(__half2*)(sEw + g       * SROW + off) = lo;
        *(__half2*)(sEw + (8 + g) * SROW + off) = hi;
    }
    __syncwarp();
    {
        int r  = lane >> 1;
        int sg = (lane & 1) * 32;
        const uint4* s = (const uint4*)(sEw + r * SROW + sg);
        uint4* d = (uint4*)(Out + (rowG + r) * 64 + sg);
        #pragma unroll
        for (int i = 0; i < 4; i++) d[i] = s[i];
    }
    __syncwarp();
}

// fp32-input GEMM (measured 33.3us): direct-LDG.64 A fragments.
// Output stored in PERMUTED layout (consumed by agg1 -> k_gemm_f16).
__global__ void __launch_bounds__(256) k_gemm_f32(const float* __restrict__ A,
                                                  const float* __restrict__ W,
                                                  __half* __restrict__ Out) {
    __shared__ __align__(16) __half sW[64 * SROW];          // 9 KB
    __shared__ __align__(16) __half sE[8][16 * SROW];       // 18 KB
    const int tid  = threadIdx.x;
    const int w    = tid >> 5;
    const int lane = tid & 31;
    const int g    = lane >> 2, tg = lane & 3;
    const int grp  = lane >> 3, gr = lane & 7;
    const int tile0 = blockIdx.x * TPB;

    load_w_conv(W, sW, tid);

    const unsigned bBase = smem_u32(sW)
        + ((gr + (grp & 1) * 8) * SROW + (grp >> 1) * 8) * 2;
    __half* sEw = &sE[w][0];
    const int m0 = w * 16;

    float2 raw[16];
    {
        const float* base = A + ((size_t)tile0 * 128 + m0) * 64;
        #pragma unroll
        for (int ks = 0; ks < 4; ks++)
            #pragma unroll
            for (int f = 0; f < 4; f++)
                raw[ks * 4 + f] = __ldg((const float2*)
                    (base + (g + (f & 1) * 8) * 64 + ks * 16 + 2 * tg + (f >> 1) * 8));
    }
    __syncthreads();   // sW ready

    #pragma unroll
    for (int it = 0; it < TPB; it++) {
        unsigned a[4][4];
        #pragma unroll
        for (int ks = 0; ks < 4; ks++)
            #pragma unroll
            for (int f = 0; f < 4; f++) {
                __half2 h = __float22half2_rn(raw[ks * 4 + f]);
                a[ks][f] = *(unsigned*)&h;
            }
        if (it + 1 < TPB) {
            const float* base = A + ((size_t)(tile0 + it + 1) * 128 + m0) * 64;
            #pragma unroll
            for (int ks = 0; ks < 4; ks++)
                #pragma unroll
                for (int f = 0; f < 4; f++)
                    raw[ks * 4 + f] = __ldg((const float2*)
                        (base + (g + (f & 1) * 8) * 64 + ks * 16 + 2 * tg + (f >> 1) * 8));
        }
        mma_tile(a, bBase, sEw, Out, (size_t)(tile0 + it) * 128 + m0, lane, 1);
    }
}

// fp16-input GEMM: A stored PERMUTED, so each thread's (a0,a2)/(a1,a3)
// fragments are one 8B LDG.64. Same structure as k_gemm_f32 (no staging,
// no block syncs in loop, register prefetch). Output in TRUE order.
__global__ void __launch_bounds__(256) k_gemm_f16(const __half* __restrict__ A,
                                                  const float* __restrict__ W,
                                                  __half* __restrict__ Out) {
    __shared__ __align__(16) __half sW[64 * SROW];          // 9 KB
    __shared__ __align__(16) __half sE[8][16 * SROW];       // 18 KB
    const int tid  = threadIdx.x;
    const int w    = tid >> 5;
    const int lane = tid & 31;
    const int g    = lane >> 2, tg = lane & 3;
    const int grp  = lane >> 3, gr = lane & 7;
    const int tile0 = blockIdx.x * TPB;

    load_w_conv(W, sW, tid);

    const unsigned bBase = smem_u32(sW)
        + ((gr + (grp & 1) * 8) * SROW + (grp >> 1) * 8) * 2;
    __half* sEw = &sE[w][0];
    const int m0 = w * 16;

    ull raw[8];
    {
        const __half* base = A + ((size_t)tile0 * 128 + m0) * 64;
        #pragma unroll
        for (int ks = 0; ks < 4; ks++)
            #pragma unroll
            for (int r = 0; r < 2; r++)
                raw[ks * 2 + r] = __ldg((const ull*)
                    (base + (g + r * 8) * 64 + ks * 16 + tg * 4));
    }
    __syncthreads();   // sW ready

    #pragma unroll
    for (int it = 0; it < TPB; it++) {
        unsigned a[4][4];
        #pragma unroll
        for (int ks = 0; ks < 4; ks++) {
            unpack_u64(raw[ks * 2 + 0], a[ks][0], a[ks][2]);   // row g:   a0, a2
            unpack_u64(raw[ks * 2 + 1], a[ks][1], a[ks][3]);   // row g+8: a1, a3
        }
        if (it + 1 < TPB) {
            const __half* base = A + ((size_t)(tile0 + it + 1) * 128 + m0) * 64;
            #pragma unroll
            for (int ks = 0; ks < 4; ks++)
                #pragma unroll
                for (int r = 0; r < 2; r++)
                    raw[ks * 2 + r] = __ldg((const ull*)
                        (base + (g + r * 8) * 64 + ks * 16 + tg * 4));
        }
        mma_tile(a, bBase, sEw, Out, (size_t)(tile0 + it) * 128 + m0, lane, 0);
    }
}

// -------- aggregation (R14 config): block = (4 nodes, 8 t-values), tg-major;
// split-lane LDG.64 gathers; fp32 accumulate. Layout-covariant: output uses
// the SAME column layout as input (wide 8B/16B stores either way). bias_perm
// selects permuted bias lookup (agg1: permuted hidden layout) vs true (agg2). --------
__global__ void __launch_bounds__(256) k_agg(const __half* __restrict__ in,
                                             const float* __restrict__ bias,
                                             void* __restrict__ out,
                                             int do_relu, int out_fp16,
                                             int bias_perm) {
    __shared__ int2 se[4 * CAP];
    __shared__ int  sc[4];
    const int bid  = blockIdx.x;
    const int tg   = bid / (N_NODES / 4);          // 0..3
    const int n0   = (bid - tg * (N_NODES / 4)) * 4;
    const int tid  = threadIdx.x;

    {
        int j = tid >> 6, k = tid & 63;
        int c = g_count[n0 + j];
        if (c > CAP) c = CAP;
        if (k == 0) sc[j] = c;
        if (k < c) se[tid] = g_csr[(n0 + j) * CAP + k];
    }
    __syncthreads();

    const int w    = tid >> 5;
    const int lane = tid & 31;
    const int half = lane >> 4;
    const int hl   = lane & 15;
    const int t    = tg * 8 + w;

    const ull* base = (const ull*)(in + (size_t)t * (N_NODES * F_DIM)) + hl;

    // bias for the two column-pairs this lane holds
    float4 bv;
    if (bias_perm) {
        // permuted layout: ull hl = true pairs (8*(hl>>2)+(hl&3), +4)
        int t0 = 8 * (hl >> 2) + (hl & 3);
        float2 b0 = __ldg((const float2*)bias + t0);
        float2 b1 = __ldg((const float2*)bias + t0 + 4);
        bv = make_float4(b0.x, b0.y, b1.x, b1.y);
    } else {
        bv = __ldg((const float4*)bias + hl);
    }

    #pragma unroll
    for (int j = 0; j < 4; j++) {
        const int cnt = sc[j];
        const int2* sej = se + j * CAP;

        ull a0 = 0ull, a1 = 0ull, a2 = 0ull, a3 = 0ull;
        int e = 0;
        for (; e + 7 < cnt; e += 8) {
            int2 s0 = sej[e     + half];
            int2 s1 = sej[e + 2 + half];
            int2 s2 = sej[e + 4 + half];
            int2 s3 = sej[e + 6 + half];
            ull v0 = __ldg(base + (unsigned)s0.x * 16u);
            ull v1 = __ldg(base + (unsigned)s1.x * 16u);
            ull v2 = __ldg(base + (unsigned)s2.x * 16u);
            ull v3 = __ldg(base + (unsigned)s3.x * 16u);
            float w0 = __int_as_float(s0.y), w1 = __int_as_float(s1.y);
            float w2 = __int_as_float(s2.y), w3 = __int_as_float(s3.y);
            {   const __half2* h = (const __half2*)&v0;
                float2 f0 = __half22float2(h[0]), f1 = __half22float2(h[1]);
                a0 = fma2(pack2(w0, w0), pack2(f0.x, f0.y), a0);
                a1 = fma2(pack2(w0, w0), pack2(f1.x, f1.y), a1); }
            {   const __half2* h = (const __half2*)&v1;
                float2 f0 = __half22float2(h[0]), f1 = __half22float2(h[1]);
                a2 = fma2(pack2(w1, w1), pack2(f0.x, f0.y), a2);
                a3 = fma2(pack2(w1, w1), pack2(f1.x, f1.y), a3); }
            {   const __half2* h = (const __half2*)&v2;
                float2 f0 = __half22float2(h[0]), f1 = __half22float2(h[1]);
                a0 = fma2(pack2(w2, w2), pack2(f0.x, f0.y), a0);
                a1 = fma2(pack2(w2, w2), pack2(f1.x, f1.y), a1); }
            {   const __half2* h = (const __half2*)&v3;
                float2 f0 = __half22float2(h[0]), f1 = __half22float2(h[1]);
                a2 = fma2(pack2(w3, w3), pack2(f0.x, f0.y), a2);
                a3 = fma2(pack2(w3, w3), pack2(f1.x, f1.y), a3); }
        }
        for (; e < cnt; e += 2) {
            int idx = e + half;
            if (idx < cnt) {
                int2 sn = sej[idx];
                ull v = __ldg(base + (unsigned)sn.x * 16u);
                float ww = __int_as_float(sn.y);
                const __half2* h = (const __half2*)&v;
                float2 f0 = __half22float2(h[0]), f1 = __half22float2(h[1]);
                a0 = fma2(pack2(ww, ww), pack2(f0.x, f0.y), a0);
                a1 = fma2(pack2(ww, ww), pack2(f1.x, f1.y), a1);
            }
        }

        a0 = add2(a0, a2);
        a1 = add2(a1, a3);
        ull b0 = __shfl_down_sync(0xffffffffu, a0, 16);
        ull b1 = __shfl_down_sync(0xffffffffu, a1, 16);
        if (half == 0) {
            a0 = add2(a0, b0);
            a1 = add2(a1, b1);
            float2 p0 = unpack2(a0), p1 = unpack2(a1);
            float4 o = make_float4(p0.x + bv.x, p0.y + bv.y,
                                   p1.x + bv.z, p1.y + bv.w);
            if (do_relu) {
                o.x = fmaxf(o.x, 0.f); o.y = fmaxf(o.y, 0.f);
                o.z = fmaxf(o.z, 0.f); o.w = fmaxf(o.w, 0.f);
            }
            const size_t rrow = (size_t)t * N_NODES + (n0 + j);
            if (out_fp16) {
                ((ull*)out)[rrow * 16 + hl] = f4_to_h4(o.x, o.y, o.z, o.w);
            } else {
                ((float4*)out)[rrow * 16 + hl] = o;
            }
        }
    }
}

// -------- launch --------
extern "C" void kernel_launch(void* const* d_in, const int* in_sizes, int n_in,
                              void* d_out, int out_size) {
    const float* x   = (const float*)d_in[0];
    const void*  ei  = d_in[1];
    const float* ew  = (const float*)d_in[2];
    const float* W1  = (const float*)d_in[3];
    const float* b1  = (const float*)d_in[4];
    const float* W2  = (const float*)d_in[5];
    const float* b2  = (const float*)d_in[6];
    float*       out = (float*)d_out;

    __half *h1 = nullptr, *h2 = nullptr;
    cudaGetSymbolAddress((void**)&h1, g_h1);
    cudaGetSymbolAddress((void**)&h2, g_h2);

    k_detect_init<<<(E_EDGES + 255) / 256, 256>>>(ei);       // 0
    k_hist       <<<(E_EDGES + 255) / 256, 256>>>(ei, ew);   // 1
    k_fill       <<<(E_EDGES + 255) / 256, 256>>>(ei, ew);   // 2

    // layer 1: h = relu(A (x W1) + b1)   [h fp16, PERMUTED layout throughout]
    k_gemm_f32<<<NTILES / TPB, 256>>>(x, W1, h1);            // 3  (ncu target)
    k_agg     <<<(N_NODES / 4) * 4, 256>>>(h1, b1, h2, 1, 1, 1);   // 4
    // layer 2: out = A (h W2) + b2       [true order from gemm_f16 onward]
    k_gemm_f16<<<NTILES / TPB, 256>>>(h2, W2, h1);           // 5
    k_agg     <<<(N_NODES / 4) * 4, 256>>>(h1, b2, out, 0, 0, 0);  // 6
}